// round 4
// baseline (speedup 1.0000x reference)
#include <cuda_runtime.h>
#include <math.h>

#define Bn 32
#define Sn 512
#define Hn 768
#define FDn 64
#define Pn 30
#define NROWS (Bn*Sn)    // 16384
#define NBLK 148
#define KSn 4

typedef unsigned long long u64;

__device__ __forceinline__ void fma2(u64 &d, u64 a, u64 b) {
    asm("fma.rn.f32x2 %0, %1, %2, %0;" : "+l"(d) : "l"(a), "l"(b));
}
__device__ __forceinline__ void add2(u64 &d, u64 a) {
    asm("add.rn.f32x2 %0, %0, %1;" : "+l"(d) : "l"(a));
}
__device__ __forceinline__ u64 rep2(float a) {
    u64 r; asm("mov.b64 %0, {%1, %1};" : "=l"(r) : "f"(a)); return r;
}
__device__ __forceinline__ float2 unpk(u64 v) {
    float2 f; asm("mov.b64 {%0, %1}, %2;" : "=f"(f.x), "=f"(f.y) : "l"(v)); return f;
}

// ------------------ scratch ------------------
__device__ float g_WT [Hn * 32];
__device__ float g_WaT[FDn * 32];
__device__ float g_pt [KSn * NROWS * 32];   // 8.4 MB partials
__device__ float g_textT [Bn * 32 * Sn];
__device__ float g_audioT[Bn * 32 * Sn];
__device__ float g_part[128];
__device__ float g_raw0[Bn * Sn];
__device__ float g_avp[Bn * 16 * Hn];
__device__ float g_h[Bn * Hn];
__device__ unsigned int g_barcnt = 0;

// grid barrier: monotonic counter, replay-safe, no reset needed
__device__ __forceinline__ void gridbar() {
    __syncthreads();
    if (threadIdx.x == 0) {
        __threadfence();
        unsigned arrive = atomicAdd(&g_barcnt, 1);
        unsigned target = (arrive / NBLK + 1u) * NBLK;
        while ((int)(*(volatile unsigned int*)&g_barcnt - target) < 0) { }
        __threadfence();
    }
    __syncthreads();
}

__global__ __launch_bounds__(256) void k_all(
    const float* __restrict__ hs, const float* __restrict__ ad,
    const float* __restrict__ am, const float* __restrict__ Wt,
    const float* __restrict__ Wa, const float* __restrict__ twp,
    const float* __restrict__ awp, const float* __restrict__ fbp,
    const float* __restrict__ Wd, const float* __restrict__ bd,
    const float* __restrict__ lw, const float* __restrict__ lb,
    float* __restrict__ out_h0, float* __restrict__ out_ta,
    float* __restrict__ out_fa)
{
    __shared__ __align__(16) float S[11008];
    int tid = threadIdx.x, blk = blockIdx.x;

    // ================= S0: weight transpose =================
    for (int e = blk * 256 + tid; e < 26624; e += NBLK * 256) {
        if (e < 24576) { int p = e & 31, k = e >> 5; g_WT[e]  = (p < Pn) ? Wt[p * Hn  + k] : 0.f; }
        else { int e2 = e - 24576; int p = e2 & 31, k = e2 >> 5; g_WaT[e2] = (p < Pn) ? Wa[p * FDn + k] : 0.f; }
    }
    gridbar();

    // ================= S1: text proj partials (K-split 4) =================
    {
        int sub = tid >> 7, stid = tid & 127;
        int rthr = stid >> 2, pthr = stid & 3;
        float* sA = S + sub * 4864;          // 256 x 17
        float* sW = sA + 4352;               // 16 x 32
        int u = sub + 2 * blk;
        bool act = (u < 256);
        int rowblk = u & 63, ks = u >> 6;
        int row0 = rowblk * 256, kbase = ks * 192;

        u64 acc[8][4];
        #pragma unroll
        for (int i = 0; i < 8; i++)
            #pragma unroll
            for (int j = 0; j < 4; j++) acc[i][j] = 0ull;

        for (int cc = 0; cc < 12; cc++) {
            int kb = kbase + cc * 16;
            __syncthreads();
            if (act) {
                #pragma unroll
                for (int q = 0; q < 8; q++) {
                    int e = stid + 128 * q;
                    int r = e >> 2, k4 = e & 3;
                    float4 v = ((const float4*)hs)[(size_t)(row0 + r) * 192 + (kb >> 2) + k4];
                    float* d = &sA[r * 17 + k4 * 4];
                    d[0] = v.x; d[1] = v.y; d[2] = v.z; d[3] = v.w;
                }
                int k = stid >> 3, p4 = stid & 7;
                float4 v = ((const float4*)g_WT)[(kb + k) * 8 + p4];
                *(float4*)&sW[k * 32 + p4 * 4] = v;
            }
            __syncthreads();
            if (act) {
                #pragma unroll
                for (int k = 0; k < 16; k++) {
                    u64 w[4];
                    #pragma unroll
                    for (int j = 0; j < 4; j++)
                        w[j] = *(const u64*)&sW[k * 32 + pthr * 8 + 2 * j];
                    #pragma unroll
                    for (int i = 0; i < 8; i++) {
                        u64 a = rep2(sA[(rthr * 8 + i) * 17 + k]);
                        fma2(acc[i][0], a, w[0]); fma2(acc[i][1], a, w[1]);
                        fma2(acc[i][2], a, w[2]); fma2(acc[i][3], a, w[3]);
                    }
                }
            }
        }
        if (act) {
            #pragma unroll
            for (int i = 0; i < 8; i++) {
                size_t base = (size_t)ks * (NROWS * 32) +
                              (size_t)(row0 + rthr * 8 + i) * 32 + pthr * 8;
                u64* d = (u64*)&g_pt[base];
                d[0] = acc[i][0]; d[1] = acc[i][1]; d[2] = acc[i][2]; d[3] = acc[i][3];
            }
        }
    }
    gridbar();

    // ================= S2: finalize (sum partials + audio GEMM + transpose) =================
    if (blk < 128) {
        float* sAa = S;                 // 128 x 68
        float* sWa = S + 8704;          // 64 x 32
        float* red = S + 10752;         // 256
        float* sX  = S;                 // 32 x 129 alias

        int rthr = tid >> 2, pthr = tid & 3;
        int row0 = blk * 128;
        int b = row0 >> 9, sbase = row0 & 511;

        #pragma unroll
        for (int q = 0; q < 8; q++) {
            int e = tid + 256 * q;
            int r = e >> 4, c = e & 15;
            float4 v = ((const float4*)ad)[(size_t)(row0 + r) * 16 + c];
            *(float4*)&sAa[r * 68 + c * 4] = v;
        }
        #pragma unroll
        for (int q = 0; q < 2; q++) {
            int e = tid + 256 * q;
            int k = e >> 3, p4 = e & 7;
            float4 v = ((const float4*)g_WaT)[k * 8 + p4];
            *(float4*)&sWa[k * 32 + p4 * 4] = v;
        }
        __syncthreads();

        u64 aacc[2][4];
        #pragma unroll
        for (int i = 0; i < 2; i++)
            #pragma unroll
            for (int j = 0; j < 4; j++) aacc[i][j] = 0ull;
        #pragma unroll 8
        for (int k = 0; k < 64; k++) {
            u64 w[4];
            #pragma unroll
            for (int j = 0; j < 4; j++)
                w[j] = *(const u64*)&sWa[k * 32 + pthr * 8 + 2 * j];
            #pragma unroll
            for (int i = 0; i < 2; i++) {
                u64 a = rep2(sAa[(rthr * 2 + i) * 68 + k]);
                fma2(aacc[i][0], a, w[0]); fma2(aacc[i][1], a, w[1]);
                fma2(aacc[i][2], a, w[2]); fma2(aacc[i][3], a, w[3]);
            }
        }

        u64 tacc[2][4];
        #pragma unroll
        for (int i = 0; i < 2; i++) {
            size_t base = (size_t)(row0 + rthr * 2 + i) * 32 + pthr * 8;
            #pragma unroll
            for (int j = 0; j < 4; j++) tacc[i][j] = 0ull;
            #pragma unroll
            for (int ks = 0; ks < KSn; ks++) {
                const u64* s = (const u64*)&g_pt[(size_t)ks * (NROWS * 32) + base];
                add2(tacc[i][0], s[0]); add2(tacc[i][1], s[1]);
                add2(tacc[i][2], s[2]); add2(tacc[i][3], s[3]);
            }
        }

        float sumsq = 0.f;
        #pragma unroll
        for (int i = 0; i < 2; i++)
            #pragma unroll
            for (int j = 0; j < 4; j++) {
                float2 f = unpk(tacc[i][j]);
                sumsq += f.x * f.x + f.y * f.y;
            }
        red[tid] = sumsq;
        __syncthreads();

        // transpose text
        #pragma unroll
        for (int i = 0; i < 2; i++)
            #pragma unroll
            for (int j = 0; j < 4; j++) {
                float2 f = unpk(tacc[i][j]);
                int s = rthr * 2 + i;
                sX[(pthr * 8 + 2 * j)     * 129 + s] = f.x;
                sX[(pthr * 8 + 2 * j + 1) * 129 + s] = f.y;
            }
        __syncthreads();
        #pragma unroll
        for (int q = 0; q < 16; q++) {
            int e = tid + 256 * q;
            int p = e >> 7, c = e & 127;
            g_textT[(size_t)(b * 32 + p) * 512 + sbase + c] = sX[p * 129 + c];
        }
        __syncthreads();
        // transpose audio
        #pragma unroll
        for (int i = 0; i < 2; i++)
            #pragma unroll
            for (int j = 0; j < 4; j++) {
                float2 f = unpk(aacc[i][j]);
                int s = rthr * 2 + i;
                sX[(pthr * 8 + 2 * j)     * 129 + s] = f.x;
                sX[(pthr * 8 + 2 * j + 1) * 129 + s] = f.y;
            }
        __syncthreads();
        #pragma unroll
        for (int q = 0; q < 16; q++) {
            int e = tid + 256 * q;
            int p = e >> 7, c = e & 127;
            g_audioT[(size_t)(b * 32 + p) * 512 + sbase + c] = sX[p * 129 + c];
        }

        __syncthreads();
        for (int s = 128; s > 0; s >>= 1) {
            if (tid < s) red[tid] += red[tid + s];
            __syncthreads();
        }
        if (tid == 0) g_part[blk] = red[0];
    }
    gridbar();

    // ================= S3: scores =================
    {
        // block-local norm scale
        if (tid < 32) {
            float v = g_part[tid] + g_part[tid + 32] + g_part[tid + 64] + g_part[tid + 96];
            #pragma unroll
            for (int o = 16; o > 0; o >>= 1) v += __shfl_xor_sync(0xffffffff, v, o);
            if (tid == 0) S[10752] = rsqrtf(v);
        }
        __syncthreads();
        float cs = S[10752];
        float tw = twp[0], aw = awp[0], fb = fbp[0];

        int warp = tid >> 5, lane = tid & 31;
        int m = warp >> 2;                       // 0 text, 1 audio
        int idx = ((warp & 3) << 5) | lane;      // 0..127
        int sthr = idx >> 3, tthr = idx & 7;
        float* xch = S;                          // 64 x 65 alias

        for (int it = 0; it < 8; it++) {
            int unit = blk + NBLK * it;
            bool act = (unit < 1152);
            int x = 0, b = 0, si = 0, ti = 0, s0 = 0, t0 = 0;
            if (act) {
                x = unit % 36; b = unit / 36;
                while (x >= 8 - si) { x -= 8 - si; si++; }
                ti = si + x; s0 = si * 64; t0 = ti * 64;
            }
            if (act) {
                const float4* gT = (const float4*)(g_textT  + (size_t)b * 16384);
                const float4* gA = (const float4*)(g_audioT + (size_t)b * 16384);
                #pragma unroll
                for (int q = 0; q < 8; q++) {
                    int e = tid + 256 * q;
                    int tile = e >> 9, id2 = e & 511;
                    int p = id2 >> 4, c = id2 & 15;
                    const float4* src = (tile < 2) ? gT : gA;
                    int off = (tile & 1) ? (t0 >> 2) : (s0 >> 2);
                    ((float4*)S)[tile * 512 + p * 16 + c] = src[p * 128 + off + c];
                }
            }
            __syncthreads();

            u64 acc[4][4];
            #pragma unroll
            for (int i = 0; i < 4; i++)
                #pragma unroll
                for (int j = 0; j < 4; j++) acc[i][j] = 0ull;
            if (act) {
                const float* sS = S + m * 4096;
                const float* sT = sS + 2048;
                #pragma unroll 5
                for (int p = 0; p < Pn; p++) {
                    const float* ps = sS + p * 64 + sthr * 4;
                    const float* pt = sT + p * 64 + tthr * 8;
                    u64 t0v = *(const u64*)(pt);
                    u64 t1v = *(const u64*)(pt + 2);
                    u64 t2v = *(const u64*)(pt + 4);
                    u64 t3v = *(const u64*)(pt + 6);
                    #pragma unroll
                    for (int i = 0; i < 4; i++) {
                        u64 a = rep2(ps[i]);
                        fma2(acc[i][0], a, t0v); fma2(acc[i][1], a, t1v);
                        fma2(acc[i][2], a, t2v); fma2(acc[i][3], a, t3v);
                    }
                }
            }
            __syncthreads();

            float tav[4][8];
            if (act) {
                if (m == 1) {
                    #pragma unroll
                    for (int i = 0; i < 4; i++) {
                        float* row = xch + (sthr * 4 + i) * 65 + tthr * 8;
                        #pragma unroll
                        for (int j = 0; j < 4; j++) {
                            float2 f = unpk(acc[i][j]);
                            row[2 * j]     = fmaxf(f.x, 0.f);
                            row[2 * j + 1] = fmaxf(f.y, 0.f);
                        }
                    }
                } else {
                    #pragma unroll
                    for (int i = 0; i < 4; i++)
                        #pragma unroll
                        for (int j = 0; j < 4; j++) {
                            float2 f = unpk(acc[i][j]);
                            tav[i][2 * j]     = fmaxf(f.x * cs, 0.f);
                            tav[i][2 * j + 1] = fmaxf(f.y * cs, 0.f);
                        }
                }
            }
            __syncthreads();

            if (act && m == 0) {
                #pragma unroll
                for (int i = 0; i < 4; i++) {
                    int s = s0 + sthr * 4 + i;
                    const float* arow = xch + (sthr * 4 + i) * 65 + tthr * 8;
                    size_t base = ((size_t)(b * Sn + s)) * Sn + t0 + tthr * 8;
                    float fa[8], rw[8];
                    #pragma unroll
                    for (int j = 0; j < 8; j++) {
                        float r_ = tw * tav[i][j] + aw * arow[j] + fb;
                        rw[j] = r_; fa[j] = fmaxf(r_, 0.f);
                    }
                    *(float4*)(out_ta + base)     = make_float4(tav[i][0], tav[i][1], tav[i][2], tav[i][3]);
                    *(float4*)(out_ta + base + 4) = make_float4(tav[i][4], tav[i][5], tav[i][6], tav[i][7]);
                    *(float4*)(out_fa + base)     = make_float4(fa[0], fa[1], fa[2], fa[3]);
                    *(float4*)(out_fa + base + 4) = make_float4(fa[4], fa[5], fa[6], fa[7]);
                    if (si == 0 && sthr == 0 && i == 0) {
                        *(float4*)(g_raw0 + b * Sn + t0 + tthr * 8)     = make_float4(rw[0], rw[1], rw[2], rw[3]);
                        *(float4*)(g_raw0 + b * Sn + t0 + tthr * 8 + 4) = make_float4(rw[4], rw[5], rw[6], rw[7]);
                    }
                }
                if (si != ti) {
                    #pragma unroll
                    for (int j = 0; j < 8; j++) {
                        int t = t0 + tthr * 8 + j;
                        size_t base = ((size_t)(b * Sn + t)) * Sn + s0 + sthr * 4;
                        float fa[4];
                        #pragma unroll
                        for (int i = 0; i < 4; i++) {
                            float a_ = xch[(sthr * 4 + i) * 65 + tthr * 8 + j];
                            fa[i] = fmaxf(tw * tav[i][j] + aw * a_ + fb, 0.f);
                        }
                        *(float4*)(out_ta + base) = make_float4(tav[0][j], tav[1][j], tav[2][j], tav[3][j]);
                        *(float4*)(out_fa + base) = make_float4(fa[0], fa[1], fa[2], fa[3]);
                    }
                }
            }
            __syncthreads();
        }
    }
    gridbar();

    // ================= S4: softmax + AV partials =================
    for (int it = 0; it < 4; it++) {
        int unit = blk + NBLK * it;
        if (unit < 512) {
            int b = unit >> 4, cy = unit & 15, t0c = cy * 32;
            float* sp  = S;
            float* red = S + 512;
            float mbase = am[b * Sn];
            float l0 = g_raw0[b * Sn + tid]       + am[b * Sn + tid]       + mbase;
            float l1 = g_raw0[b * Sn + tid + 256] + am[b * Sn + tid + 256] + mbase;
            red[tid] = fmaxf(l0, l1);
            __syncthreads();
            for (int s = 128; s > 0; s >>= 1) {
                if (tid < s) red[tid] = fmaxf(red[tid], red[tid + s]);
                __syncthreads();
            }
            float mx = red[0];
            __syncthreads();
            float e0 = expf(l0 - mx), e1 = expf(l1 - mx);
            red[tid] = e0 + e1;
            __syncthreads();
            for (int s = 128; s > 0; s >>= 1) {
                if (tid < s) red[tid] += red[tid + s];
                __syncthreads();
            }
            float inv = 1.f / red[0];
            __syncthreads();
            sp[tid] = e0 * inv; sp[tid + 256] = e1 * inv;
            __syncthreads();

            if (tid < 192) {
                const float4* hb = (const float4*)(hs + (size_t)b * Sn * Hn);
                float4 acc = make_float4(0.f, 0.f, 0.f, 0.f);
                #pragma unroll 8
                for (int t = 0; t < 32; t++) {
                    float p = sp[t0c + t];
                    float4 h = hb[(size_t)(t0c + t) * 192 + tid];
                    acc.x += p * h.x; acc.y += p * h.y; acc.z += p * h.z; acc.w += p * h.w;
                }
                ((float4*)g_avp)[(size_t)(b * 16 + cy) * 192 + tid] = acc;
            }
            __syncthreads();
        }
    }
    gridbar();

    // ================= S5: dense GEMV =================
    for (int it = 0; it < 2; it++) {
        int unit = blk + NBLK * it;
        if (unit < 256) {
            int b = unit >> 3, oc = unit & 7;
            float* sx = S;
            for (int i = tid; i < Hn; i += 256) {
                float v = hs[(size_t)b * Sn * Hn + i];
                #pragma unroll
                for (int c = 0; c < 16; c++) v += g_avp[(size_t)(b * 16 + c) * Hn + i];
                sx[i] = v;
            }
            __syncthreads();
            int w = tid >> 5, lane = tid & 31;
            const float4* sx4 = (const float4*)sx;
            #pragma unroll
            for (int q = 0; q < 12; q++) {
                int o = oc * 96 + w * 12 + q;
                const float4* w4 = (const float4*)(Wd + (size_t)o * Hn);
                float acc = 0.f;
                #pragma unroll
                for (int c = 0; c < 6; c++) {
                    float4 wv = w4[c * 32 + lane];
                    float4 xv = sx4[c * 32 + lane];
                    acc += wv.x * xv.x + wv.y * xv.y + wv.z * xv.z + wv.w * xv.w;
                }
                #pragma unroll
                for (int s = 16; s > 0; s >>= 1)
                    acc += __shfl_down_sync(0xffffffff, acc, s);
                if (lane == 0) g_h[b * Hn + o] = acc + bd[o];
            }
            __syncthreads();
        }
    }
    gridbar();

    // ================= S6: layernorm =================
    if (blk < 32) {
        int b = blk;
        float* red = S;
        float hv[3];
        #pragma unroll
        for (int j = 0; j < 3; j++) hv[j] = g_h[b * Hn + tid + 256 * j];
        red[tid] = hv[0] + hv[1] + hv[2];
        __syncthreads();
        for (int s = 128; s > 0; s >>= 1) {
            if (tid < s) red[tid] += red[tid + s];
            __syncthreads();
        }
        float u = red[0] / (float)Hn;
        __syncthreads();
        float vs = 0.f;
        #pragma unroll
        for (int j = 0; j < 3; j++) { float d = hv[j] - u; vs += d * d; }
        red[tid] = vs;
        __syncthreads();
        for (int s = 128; s > 0; s >>= 1) {
            if (tid < s) red[tid] += red[tid + s];
            __syncthreads();
        }
        float rstd = rsqrtf(red[0] / (float)Hn + 1e-12f);
        #pragma unroll
        for (int j = 0; j < 3; j++) {
            int o = tid + 256 * j;
            out_h0[b * Hn + o] = lw[o] * (hv[j] - u) * rstd + lb[o];
        }
    }
}

// ------------------ launch ------------------
extern "C" void kernel_launch(void* const* d_in, const int* in_sizes, int n_in,
                              void* d_out, int out_size) {
    const float* hs = (const float*)d_in[0];
    const float* ad = (const float*)d_in[1];
    const float* am = (const float*)d_in[2];
    const float* Wt = (const float*)d_in[3];
    const float* Wa = (const float*)d_in[4];
    const float* tw = (const float*)d_in[5];
    const float* aw = (const float*)d_in[6];
    const float* fb = (const float*)d_in[7];
    const float* Wd = (const float*)d_in[8];
    const float* bd = (const float*)d_in[9];
    const float* lw = (const float*)d_in[10];
    const float* lb = (const float*)d_in[11];

    float* out    = (float*)d_out;
    float* out_h0 = out;
    float* out_ta = out + Bn * Hn;
    float* out_fa = out + Bn * Hn + (size_t)Bn * Sn * Sn;

    k_all<<<NBLK, 256>>>(hs, ad, am, Wt, Wa, tw, aw, fb, Wd, bd, lw, lb,
                         out_h0, out_ta, out_fa);
}